// round 1
// baseline (speedup 1.0000x reference)
#include <cuda_runtime.h>
#include <cstdint>

// Vector quantizer: for each z row (D=64), find argmin_k ||z - e_k||^2 over K codes,
// output z_q = codebook[argmin] and the indices.
//
// Distance replicated exactly as the reference formula (fp32):
//   d = (z2 - 2*dot) + e2     with z2 = sum(z_i^2) (square then add, unfused)
//
// Strategy: FMA-bound problem -> use packed fp32 FMA (fma.rn.f32x2 -> FFMA2)
// to reach full fp32 rate. One thread per z row; codebook tiled through smem
// (warp-broadcast LDS, conflict free); 4 independent f32x2 accumulators.

#define DIMS 64
#define TK   128     // codes per smem tile
#define CTA  256

__device__ float g_e2[8192];   // ||e_k||^2 scratch (K <= 8192)

// ---- packed f32x2 helpers -------------------------------------------------
__device__ __forceinline__ unsigned long long fma2(unsigned long long a,
                                                   unsigned long long b,
                                                   unsigned long long c) {
    unsigned long long r;
    asm("fma.rn.f32x2 %0, %1, %2, %3;" : "=l"(r) : "l"(a), "l"(b), "l"(c));
    return r;
}
__device__ __forceinline__ unsigned long long add2(unsigned long long a,
                                                   unsigned long long b) {
    unsigned long long r;
    asm("add.rn.f32x2 %0, %1, %2;" : "=l"(r) : "l"(a), "l"(b));
    return r;
}
__device__ __forceinline__ void unpack2(unsigned long long v, float& lo, float& hi) {
    asm("mov.b64 {%0, %1}, %2;" : "=f"(lo), "=f"(hi) : "l"(v));
}
__device__ __forceinline__ unsigned long long pack2(float lo, float hi) {
    unsigned long long r;
    asm("mov.b64 %0, {%1, %2};" : "=l"(r) : "f"(lo), "f"(hi));
    return r;
}

// ---- pass 1: per-code squared norms ---------------------------------------
__global__ void e2_kernel(const float* __restrict__ cb, int K) {
    int k = blockIdx.x * blockDim.x + threadIdx.x;
    if (k >= K) return;
    const float4* row = reinterpret_cast<const float4*>(cb + (size_t)k * DIMS);
    float s = 0.f;
#pragma unroll
    for (int i = 0; i < DIMS / 4; i++) {
        float4 v = row[i];
        // square (rounded) then add (rounded) - matches sum(codebook**2)
        s = __fadd_rn(s, __fmul_rn(v.x, v.x));
        s = __fadd_rn(s, __fmul_rn(v.y, v.y));
        s = __fadd_rn(s, __fmul_rn(v.z, v.z));
        s = __fadd_rn(s, __fmul_rn(v.w, v.w));
    }
    g_e2[k] = s;
}

// ---- pass 2: main VQ kernel ------------------------------------------------
__global__ __launch_bounds__(CTA, 2)
void vq_kernel(const float* __restrict__ z, const float* __restrict__ cb,
               int N, int K, float* __restrict__ out_q, float* __restrict__ out_idx)
{
    __shared__ float s_tile[TK * DIMS];
    __shared__ float s_e2[TK];

    const int n = blockIdx.x * CTA + threadIdx.x;
    const bool active = (n < N);

    // Load this thread's z row into packed f32x2 registers; compute z2.
    unsigned long long zr[DIMS / 2];
    float z2 = 0.f;
    if (active) {
        const float4* zp = reinterpret_cast<const float4*>(z + (size_t)n * DIMS);
#pragma unroll
        for (int i = 0; i < DIMS / 4; i++) {
            float4 v = zp[i];
            z2 = __fadd_rn(z2, __fmul_rn(v.x, v.x));
            z2 = __fadd_rn(z2, __fmul_rn(v.y, v.y));
            z2 = __fadd_rn(z2, __fmul_rn(v.z, v.z));
            z2 = __fadd_rn(z2, __fmul_rn(v.w, v.w));
            zr[2 * i + 0] = pack2(v.x, v.y);
            zr[2 * i + 1] = pack2(v.z, v.w);
        }
    } else {
#pragma unroll
        for (int i = 0; i < DIMS / 2; i++) zr[i] = 0ull;
    }

    float best = 3.4e38f;
    int   bidx = 0;
    const unsigned long long zero2 = 0ull;

    for (int t0 = 0; t0 < K; t0 += TK) {
        __syncthreads();
        // Stage codebook tile (coalesced float4 copies) + e2 slice.
        {
            const float4* cp = reinterpret_cast<const float4*>(cb + (size_t)t0 * DIMS);
            float4* sp = reinterpret_cast<float4*>(s_tile);
#pragma unroll 4
            for (int i = threadIdx.x; i < TK * DIMS / 4; i += CTA) sp[i] = cp[i];
            if (threadIdx.x < TK) s_e2[threadIdx.x] = g_e2[t0 + threadIdx.x];
        }
        __syncthreads();

        for (int kk = 0; kk < TK; kk++) {
            const unsigned long long* cs =
                reinterpret_cast<const unsigned long long*>(s_tile + kk * DIMS);
            unsigned long long a0 = zero2, a1 = zero2, a2 = zero2, a3 = zero2;
#pragma unroll
            for (int j = 0; j < DIMS / 2; j += 4) {
                a0 = fma2(zr[j + 0], cs[j + 0], a0);
                a1 = fma2(zr[j + 1], cs[j + 1], a1);
                a2 = fma2(zr[j + 2], cs[j + 2], a2);
                a3 = fma2(zr[j + 3], cs[j + 3], a3);
            }
            unsigned long long s = add2(add2(a0, a1), add2(a2, a3));
            float lo, hi;
            unpack2(s, lo, hi);
            float dot = __fadd_rn(lo, hi);
            // (z2 - 2*dot) + e2   (2*dot exact, so fma == sub after exact mul)
            float d = __fadd_rn(__fmaf_rn(-2.f, dot, z2), s_e2[kk]);
            if (d < best) { best = d; bidx = t0 + kk; }
        }
    }

    if (active) {
        // Gather codebook row -> z_q
        const float4* crow = reinterpret_cast<const float4*>(cb + (size_t)bidx * DIMS);
        float4* orow = reinterpret_cast<float4*>(out_q + (size_t)n * DIMS);
#pragma unroll
        for (int i = 0; i < DIMS / 4; i++) orow[i] = crow[i];
        if (out_idx) out_idx[n] = (float)bidx;
    }
}

extern "C" void kernel_launch(void* const* d_in, const int* in_sizes, int n_in,
                              void* d_out, int out_size) {
    const float* z  = (const float*)d_in[0];
    const float* cb = (const float*)d_in[1];
    const int N = in_sizes[0] / DIMS;
    const int K = in_sizes[1] / DIMS;
    float* out = (float*)d_out;

    // If the flattened output also carries min_indices, they follow z_q.
    float* out_idx = nullptr;
    if ((long long)out_size >= (long long)N * DIMS + N)
        out_idx = out + (size_t)N * DIMS;

    e2_kernel<<<(K + 255) / 256, 256>>>(cb, K);
    vq_kernel<<<(N + CTA - 1) / CTA, CTA>>>(z, cb, N, K, out, out_idx);
}

// round 2
// speedup vs baseline: 1.2696x; 1.2696x over previous
#include <cuda_runtime.h>
#include <cstdint>

// VQ: argmin_k ||z_n - e_k||^2, output z_q + indices.
// R2: kill the LDS bottleneck seen in R1 ncu (L1=80.9%, fma=42.8%):
//   - shared loads widened to LDS.128 (ulonglong2)
//   - 2 z-rows per thread so each staged codebook value feeds 2 rows of FMAs
// Numerics (4-accumulator tree, unfused square-then-add, (z2-2dot)+e2) kept
// bit-identical to the passing R1 kernel.

#define DIMS 64
#define TK   128     // codes per smem tile
#define CTA  256
#define RPT  2       // rows per thread

__device__ float g_e2[8192];

typedef unsigned long long u64;

__device__ __forceinline__ u64 fma2(u64 a, u64 b, u64 c) {
    u64 r;
    asm("fma.rn.f32x2 %0, %1, %2, %3;" : "=l"(r) : "l"(a), "l"(b), "l"(c));
    return r;
}
__device__ __forceinline__ u64 add2(u64 a, u64 b) {
    u64 r;
    asm("add.rn.f32x2 %0, %1, %2;" : "=l"(r) : "l"(a), "l"(b));
    return r;
}
__device__ __forceinline__ void unpack2(u64 v, float& lo, float& hi) {
    asm("mov.b64 {%0, %1}, %2;" : "=f"(lo), "=f"(hi) : "l"(v));
}

// ---- pass 1: ||e_k||^2 ------------------------------------------------------
__global__ void e2_kernel(const float* __restrict__ cb, int K) {
    int k = blockIdx.x * blockDim.x + threadIdx.x;
    if (k >= K) return;
    const float4* row = reinterpret_cast<const float4*>(cb + (size_t)k * DIMS);
    float s = 0.f;
#pragma unroll
    for (int i = 0; i < DIMS / 4; i++) {
        float4 v = row[i];
        s = __fadd_rn(s, __fmul_rn(v.x, v.x));
        s = __fadd_rn(s, __fmul_rn(v.y, v.y));
        s = __fadd_rn(s, __fmul_rn(v.z, v.z));
        s = __fadd_rn(s, __fmul_rn(v.w, v.w));
    }
    g_e2[k] = s;
}

// ---- pass 2: main VQ ---------------------------------------------------------
__global__ __launch_bounds__(CTA, 1)
void vq_kernel(const float* __restrict__ z, const float* __restrict__ cb,
               int N, int K, float* __restrict__ out_q, float* __restrict__ out_idx)
{
    __shared__ float s_tile[TK * DIMS];
    __shared__ float s_e2[TK];

    const int n0 = blockIdx.x * (CTA * RPT) + threadIdx.x;   // row 0
    const int n1 = n0 + CTA;                                  // row 1
    const bool act0 = (n0 < N);
    const bool act1 = (n1 < N);

    // z rows in packed f32x2 registers (+ unfused ||z||^2, ref order)
    u64 zr0[DIMS / 2], zr1[DIMS / 2];
    float z20 = 0.f, z21 = 0.f;
    {
        const ulonglong2* zp0 = reinterpret_cast<const ulonglong2*>(z + (size_t)(act0 ? n0 : 0) * DIMS);
        const ulonglong2* zp1 = reinterpret_cast<const ulonglong2*>(z + (size_t)(act1 ? n1 : 0) * DIMS);
#pragma unroll
        for (int i = 0; i < DIMS / 4; i++) {
            ulonglong2 a = zp0[i];
            ulonglong2 b = zp1[i];
            zr0[2 * i + 0] = a.x; zr0[2 * i + 1] = a.y;
            zr1[2 * i + 0] = b.x; zr1[2 * i + 1] = b.y;
            float x0, y0, x1, y1;
            unpack2(a.x, x0, y0); z20 = __fadd_rn(z20, __fmul_rn(x0, x0)); z20 = __fadd_rn(z20, __fmul_rn(y0, y0));
            unpack2(a.y, x0, y0); z20 = __fadd_rn(z20, __fmul_rn(x0, x0)); z20 = __fadd_rn(z20, __fmul_rn(y0, y0));
            unpack2(b.x, x1, y1); z21 = __fadd_rn(z21, __fmul_rn(x1, x1)); z21 = __fadd_rn(z21, __fmul_rn(y1, y1));
            unpack2(b.y, x1, y1); z21 = __fadd_rn(z21, __fmul_rn(x1, x1)); z21 = __fadd_rn(z21, __fmul_rn(y1, y1));
        }
    }

    float best0 = 3.4e38f, best1 = 3.4e38f;
    int   bidx0 = 0,       bidx1 = 0;

    for (int t0 = 0; t0 < K; t0 += TK) {
        __syncthreads();
        {   // stage codebook tile + e2 slice (coalesced float4)
            const float4* cp = reinterpret_cast<const float4*>(cb + (size_t)t0 * DIMS);
            float4* sp = reinterpret_cast<float4*>(s_tile);
#pragma unroll 4
            for (int i = threadIdx.x; i < TK * DIMS / 4; i += CTA) sp[i] = cp[i];
            if (threadIdx.x < TK) s_e2[threadIdx.x] = g_e2[t0 + threadIdx.x];
        }
        __syncthreads();

        for (int kk = 0; kk < TK; kk++) {
            const ulonglong2* cs =
                reinterpret_cast<const ulonglong2*>(s_tile + kk * DIMS);
            u64 a0 = 0, a1 = 0, a2 = 0, a3 = 0;   // row0, 4-acc tree (as R1)
            u64 b0 = 0, b1 = 0, b2 = 0, b3 = 0;   // row1
#pragma unroll
            for (int j = 0; j < DIMS / 8; j++) {   // 8 iters, 2 LDS.128 each
                ulonglong2 c0 = cs[2 * j + 0];
                ulonglong2 c1 = cs[2 * j + 1];
                a0 = fma2(zr0[4 * j + 0], c0.x, a0);
                a1 = fma2(zr0[4 * j + 1], c0.y, a1);
                a2 = fma2(zr0[4 * j + 2], c1.x, a2);
                a3 = fma2(zr0[4 * j + 3], c1.y, a3);
                b0 = fma2(zr1[4 * j + 0], c0.x, b0);
                b1 = fma2(zr1[4 * j + 1], c0.y, b1);
                b2 = fma2(zr1[4 * j + 2], c1.x, b2);
                b3 = fma2(zr1[4 * j + 3], c1.y, b3);
            }
            float e2 = s_e2[kk];
            {
                u64 s = add2(add2(a0, a1), add2(a2, a3));
                float lo, hi; unpack2(s, lo, hi);
                float dot = __fadd_rn(lo, hi);
                float d = __fadd_rn(__fmaf_rn(-2.f, dot, z20), e2);
                if (d < best0) { best0 = d; bidx0 = t0 + kk; }
            }
            {
                u64 s = add2(add2(b0, b1), add2(b2, b3));
                float lo, hi; unpack2(s, lo, hi);
                float dot = __fadd_rn(lo, hi);
                float d = __fadd_rn(__fmaf_rn(-2.f, dot, z21), e2);
                if (d < best1) { best1 = d; bidx1 = t0 + kk; }
            }
        }
    }

    if (act0) {
        const float4* crow = reinterpret_cast<const float4*>(cb + (size_t)bidx0 * DIMS);
        float4* orow = reinterpret_cast<float4*>(out_q + (size_t)n0 * DIMS);
#pragma unroll
        for (int i = 0; i < DIMS / 4; i++) orow[i] = crow[i];
        if (out_idx) out_idx[n0] = (float)bidx0;
    }
    if (act1) {
        const float4* crow = reinterpret_cast<const float4*>(cb + (size_t)bidx1 * DIMS);
        float4* orow = reinterpret_cast<float4*>(out_q + (size_t)n1 * DIMS);
#pragma unroll
        for (int i = 0; i < DIMS / 4; i++) orow[i] = crow[i];
        if (out_idx) out_idx[n1] = (float)bidx1;
    }
}

extern "C" void kernel_launch(void* const* d_in, const int* in_sizes, int n_in,
                              void* d_out, int out_size) {
    const float* z  = (const float*)d_in[0];
    const float* cb = (const float*)d_in[1];
    const int N = in_sizes[0] / DIMS;
    const int K = in_sizes[1] / DIMS;
    float* out = (float*)d_out;

    float* out_idx = nullptr;
    if ((long long)out_size >= (long long)N * DIMS + N)
        out_idx = out + (size_t)N * DIMS;

    e2_kernel<<<(K + 255) / 256, 256>>>(cb, K);
    const int rows_per_block = CTA * RPT;
    vq_kernel<<<(N + rows_per_block - 1) / rows_per_block, CTA>>>(z, cb, N, K, out, out_idx);
}

// round 3
// speedup vs baseline: 2.0606x; 1.6231x over previous
#include <cuda_runtime.h>
#include <cstdint>

// VQ: argmin_k ||z_n - e_k||^2 -> z_q + indices.
// R3 vs R2 (373us, fma=53.9%, issue=45.7%):
//   - kk loop unrolled x2 so code k's epilogue/LDS latency overlaps code k+1's FMAs
//   - branchless argmin (SEL, no BSSY/BSYNC from C++ if{})
// Numerics (4-acc f32x2 tree, unfused square-then-add, (z2-2dot)+e2) unchanged
// from the rel_err=0.0 kernels.

#define DIMS 64
#define TK   128
#define CTA  256
#define RPT  2

__device__ float g_e2[8192];

typedef unsigned long long u64;

__device__ __forceinline__ u64 fma2(u64 a, u64 b, u64 c) {
    u64 r;
    asm("fma.rn.f32x2 %0, %1, %2, %3;" : "=l"(r) : "l"(a), "l"(b), "l"(c));
    return r;
}
__device__ __forceinline__ u64 add2(u64 a, u64 b) {
    u64 r;
    asm("add.rn.f32x2 %0, %1, %2;" : "=l"(r) : "l"(a), "l"(b));
    return r;
}
__device__ __forceinline__ void unpack2(u64 v, float& lo, float& hi) {
    asm("mov.b64 {%0, %1}, %2;" : "=f"(lo), "=f"(hi) : "l"(v));
}

// ---- pass 1: ||e_k||^2 ------------------------------------------------------
__global__ void e2_kernel(const float* __restrict__ cb, int K) {
    int k = blockIdx.x * blockDim.x + threadIdx.x;
    if (k >= K) return;
    const float4* row = reinterpret_cast<const float4*>(cb + (size_t)k * DIMS);
    float s = 0.f;
#pragma unroll
    for (int i = 0; i < DIMS / 4; i++) {
        float4 v = row[i];
        s = __fadd_rn(s, __fmul_rn(v.x, v.x));
        s = __fadd_rn(s, __fmul_rn(v.y, v.y));
        s = __fadd_rn(s, __fmul_rn(v.z, v.z));
        s = __fadd_rn(s, __fmul_rn(v.w, v.w));
    }
    g_e2[k] = s;
}

// ---- pass 2: main VQ ---------------------------------------------------------
__global__ __launch_bounds__(CTA, 1)
void vq_kernel(const float* __restrict__ z, const float* __restrict__ cb,
               int N, int K, float* __restrict__ out_q, float* __restrict__ out_idx)
{
    __shared__ float s_tile[TK * DIMS];
    __shared__ float s_e2[TK];

    const int n0 = blockIdx.x * (CTA * RPT) + threadIdx.x;
    const int n1 = n0 + CTA;
    const bool act0 = (n0 < N);
    const bool act1 = (n1 < N);

    u64 zr0[DIMS / 2], zr1[DIMS / 2];
    float z20 = 0.f, z21 = 0.f;
    {
        const ulonglong2* zp0 = reinterpret_cast<const ulonglong2*>(z + (size_t)(act0 ? n0 : 0) * DIMS);
        const ulonglong2* zp1 = reinterpret_cast<const ulonglong2*>(z + (size_t)(act1 ? n1 : 0) * DIMS);
#pragma unroll
        for (int i = 0; i < DIMS / 4; i++) {
            ulonglong2 a = zp0[i];
            ulonglong2 b = zp1[i];
            zr0[2 * i + 0] = a.x; zr0[2 * i + 1] = a.y;
            zr1[2 * i + 0] = b.x; zr1[2 * i + 1] = b.y;
            float x0, y0, x1, y1;
            unpack2(a.x, x0, y0); z20 = __fadd_rn(z20, __fmul_rn(x0, x0)); z20 = __fadd_rn(z20, __fmul_rn(y0, y0));
            unpack2(a.y, x0, y0); z20 = __fadd_rn(z20, __fmul_rn(x0, x0)); z20 = __fadd_rn(z20, __fmul_rn(y0, y0));
            unpack2(b.x, x1, y1); z21 = __fadd_rn(z21, __fmul_rn(x1, x1)); z21 = __fadd_rn(z21, __fmul_rn(y1, y1));
            unpack2(b.y, x1, y1); z21 = __fadd_rn(z21, __fmul_rn(x1, x1)); z21 = __fadd_rn(z21, __fmul_rn(y1, y1));
        }
    }

    float best0 = 3.4e38f, best1 = 3.4e38f;
    int   bidx0 = 0,       bidx1 = 0;

    for (int t0 = 0; t0 < K; t0 += TK) {
        __syncthreads();
        {
            const float4* cp = reinterpret_cast<const float4*>(cb + (size_t)t0 * DIMS);
            float4* sp = reinterpret_cast<float4*>(s_tile);
#pragma unroll 4
            for (int i = threadIdx.x; i < TK * DIMS / 4; i += CTA) sp[i] = cp[i];
            if (threadIdx.x < TK) s_e2[threadIdx.x] = g_e2[t0 + threadIdx.x];
        }
        __syncthreads();

#pragma unroll 2
        for (int kk = 0; kk < TK; kk++) {
            const ulonglong2* cs =
                reinterpret_cast<const ulonglong2*>(s_tile + kk * DIMS);
            const float e2  = s_e2[kk];      // hoisted: issue early
            const int  kidx = t0 + kk;

            u64 a0 = 0, a1 = 0, a2 = 0, a3 = 0;
            u64 b0 = 0, b1 = 0, b2 = 0, b3 = 0;
#pragma unroll
            for (int j = 0; j < DIMS / 8; j++) {
                ulonglong2 c0 = cs[2 * j + 0];
                ulonglong2 c1 = cs[2 * j + 1];
                a0 = fma2(zr0[4 * j + 0], c0.x, a0);
                a1 = fma2(zr0[4 * j + 1], c0.y, a1);
                a2 = fma2(zr0[4 * j + 2], c1.x, a2);
                a3 = fma2(zr0[4 * j + 3], c1.y, a3);
                b0 = fma2(zr1[4 * j + 0], c0.x, b0);
                b1 = fma2(zr1[4 * j + 1], c0.y, b1);
                b2 = fma2(zr1[4 * j + 2], c1.x, b2);
                b3 = fma2(zr1[4 * j + 3], c1.y, b3);
            }
            {
                u64 s = add2(add2(a0, a1), add2(a2, a3));
                float lo, hi; unpack2(s, lo, hi);
                float dot = __fadd_rn(lo, hi);
                float d = __fadd_rn(__fmaf_rn(-2.f, dot, z20), e2);
                bool lt = d < best0;                 // branchless: FSETP + SEL
                best0 = lt ? d    : best0;
                bidx0 = lt ? kidx : bidx0;
            }
            {
                u64 s = add2(add2(b0, b1), add2(b2, b3));
                float lo, hi; unpack2(s, lo, hi);
                float dot = __fadd_rn(lo, hi);
                float d = __fadd_rn(__fmaf_rn(-2.f, dot, z21), e2);
                bool lt = d < best1;
                best1 = lt ? d    : best1;
                bidx1 = lt ? kidx : bidx1;
            }
        }
    }

    if (act0) {
        const float4* crow = reinterpret_cast<const float4*>(cb + (size_t)bidx0 * DIMS);
        float4* orow = reinterpret_cast<float4*>(out_q + (size_t)n0 * DIMS);
#pragma unroll
        for (int i = 0; i < DIMS / 4; i++) orow[i] = crow[i];
        if (out_idx) out_idx[n0] = (float)bidx0;
    }
    if (act1) {
        const float4* crow = reinterpret_cast<const float4*>(cb + (size_t)bidx1 * DIMS);
        float4* orow = reinterpret_cast<float4*>(out_q + (size_t)n1 * DIMS);
#pragma unroll
        for (int i = 0; i < DIMS / 4; i++) orow[i] = crow[i];
        if (out_idx) out_idx[n1] = (float)bidx1;
    }
}

extern "C" void kernel_launch(void* const* d_in, const int* in_sizes, int n_in,
                              void* d_out, int out_size) {
    const float* z  = (const float*)d_in[0];
    const float* cb = (const float*)d_in[1];
    const int N = in_sizes[0] / DIMS;
    const int K = in_sizes[1] / DIMS;
    float* out = (float*)d_out;

    float* out_idx = nullptr;
    if ((long long)out_size >= (long long)N * DIMS + N)
        out_idx = out + (size_t)N * DIMS;

    e2_kernel<<<(K + 255) / 256, 256>>>(cb, K);
    const int rows_per_block = CTA * RPT;
    vq_kernel<<<(N + rows_per_block - 1) / rows_per_block, CTA>>>(z, cb, N, K, out, out_idx);
}